// round 1
// baseline (speedup 1.0000x reference)
#include <cuda_runtime.h>
#include <math.h>

#define KB 4
#define KS 2048
#define KE 1024
#define KM 256
#define KT (KB * KS)   // 8192 tokens

// ---------------- scratch (device globals; no runtime allocation) ----------
__device__ __align__(16) float g_xn[(size_t)KT * KE];          // LN1 out, reused for LN2 out
__device__ __align__(16) float g_k [(size_t)KT * KM];
__device__ __align__(16) float g_q [(size_t)KT * KM];
__device__ __align__(16) float g_v [(size_t)KT * KM];
__device__ __align__(16) float g_beta [KT];
__device__ __align__(16) float g_decay[KT];
__device__ __align__(16) float g_ro[(size_t)KT * KM];
__device__ __align__(16) float g_x2[(size_t)KT * KE];
__device__ __align__(16) float g_ffn1[(size_t)KT * 4 * KE];

// ---------------- utilities ----------------
__device__ __forceinline__ float warp_sum(float v) {
#pragma unroll
    for (int o = 16; o; o >>= 1) v += __shfl_xor_sync(0xffffffffu, v, o);
    return v;
}

__device__ __forceinline__ float gelu_exact(float v) {
    return 0.5f * v * (1.0f + erff(v * 0.70710678118654752f));
}

// ---------------- LayerNorm: one block per token, 256 threads, E=1024 -----
__global__ void ln_kernel(const float* __restrict__ x, const float* __restrict__ g,
                          const float* __restrict__ bvec, float* __restrict__ y) {
    __shared__ float red[2][8];
    const int n = blockIdx.x;
    const int tid = threadIdx.x;
    const float4 xv = ((const float4*)(x + (size_t)n * KE))[tid];
    float s  = xv.x + xv.y + xv.z + xv.w;
    float ss = xv.x * xv.x + xv.y * xv.y + xv.z * xv.z + xv.w * xv.w;
    s = warp_sum(s); ss = warp_sum(ss);
    const int wid = tid >> 5, lane = tid & 31;
    if (lane == 0) { red[0][wid] = s; red[1][wid] = ss; }
    __syncthreads();
    float st = 0.f, sst = 0.f;
#pragma unroll
    for (int w = 0; w < 8; w++) { st += red[0][w]; sst += red[1][w]; }
    const float mu  = st * (1.0f / KE);
    const float var = sst * (1.0f / KE) - mu * mu;
    const float rs  = rsqrtf(var + 1e-5f);
    const float4 gg = ((const float4*)g)[tid];
    const float4 bb = ((const float4*)bvec)[tid];
    float4 o;
    o.x = (xv.x - mu) * rs * gg.x + bb.x;
    o.y = (xv.y - mu) * rs * gg.y + bb.y;
    o.z = (xv.z - mu) * rs * gg.z + bb.z;
    o.w = (xv.w - mu) * rs * gg.w + bb.w;
    ((float4*)(y + (size_t)n * KE))[tid] = o;
}

// ---------------- postproc: l2norm k,q (in place), gates from xn ----------
__global__ void postproc_kernel(const float* __restrict__ wgw, const float* __restrict__ bgw,
                                const float* __restrict__ wgf, const float* __restrict__ bgf) {
    __shared__ float red[4][8];
    const int n = blockIdx.x;
    const int i = threadIdx.x;
    const size_t off = (size_t)n * KM + i;
    const float kv = g_k[off];
    const float qv = g_q[off];
    const float4 xv = ((const float4*)(g_xn + (size_t)n * KE))[i];
    const float4 wg = ((const float4*)wgw)[i];
    const float4 wf = ((const float4*)wgf)[i];
    float dg = xv.x * wg.x + xv.y * wg.y + xv.z * wg.z + xv.w * wg.w;
    float df = xv.x * wf.x + xv.y * wf.y + xv.z * wf.z + xv.w * wf.w;
    float sk = warp_sum(kv * kv);
    float sq = warp_sum(qv * qv);
    dg = warp_sum(dg);
    df = warp_sum(df);
    const int wid = i >> 5, lane = i & 31;
    if (lane == 0) { red[0][wid] = sk; red[1][wid] = sq; red[2][wid] = dg; red[3][wid] = df; }
    __syncthreads();
    float tk = 0.f, tq = 0.f, tg = 0.f, tf = 0.f;
#pragma unroll
    for (int w = 0; w < 8; w++) { tk += red[0][w]; tq += red[1][w]; tg += red[2][w]; tf += red[3][w]; }
    const float kn = fmaxf(sqrtf(tk), 1e-12f);
    const float qn = fmaxf(sqrtf(tq), 1e-12f);
    g_k[off] = kv / kn;
    g_q[off] = qv / qn;
    if (i == 0) {
        g_beta[n]  = 1.0f / (1.0f + expf(-(tg + bgw[0])));
        g_decay[n] = 1.0f / (1.0f + expf(-(tf + bgf[0])));
    }
}

// ---------------- scan: one warp per (batch,row); row-independent ----------
// mem[i][j]: readout_t[i] = sum_j mem[i][j]*q_t[j];  mem = d*mem + (b*v[i])*k[j]
__global__ void scan_kernel(const float* __restrict__ mem0, float* __restrict__ mem_out) {
    const int blk = blockIdx.x;
    const int b = blk >> 5;                           // batch
    const int i = ((blk & 31) << 3) + (threadIdx.x >> 5);  // row 0..255
    const int lane = threadIdx.x & 31;
    const size_t mbase = (((size_t)b * KM + i) * KM) + lane * 8;

    float m[8];
    { float4 a = *(const float4*)(mem0 + mbase);
      float4 c = *(const float4*)(mem0 + mbase + 4);
      m[0]=a.x; m[1]=a.y; m[2]=a.z; m[3]=a.w; m[4]=c.x; m[5]=c.y; m[6]=c.z; m[7]=c.w; }

    const float* kb = g_k + ((size_t)b * KS) * KM + lane * 8;
    const float* qb = g_q + ((size_t)b * KS) * KM + lane * 8;
    const float* vb = g_v + ((size_t)b * KS) * KM + i;
    const float* bb = g_beta  + (size_t)b * KS;
    const float* db = g_decay + (size_t)b * KS;
    float* ro = g_ro + ((size_t)b * KS) * KM + i;

    // software-pipelined q/k loads
    float4 qa = *(const float4*)(qb);
    float4 qc = *(const float4*)(qb + 4);
    float4 ka = *(const float4*)(kb);
    float4 kc = *(const float4*)(kb + 4);

    for (int t = 0; t < KS; t++) {
        const float4 cqa = qa, cqc = qc, cka = ka, ckc = kc;
        const float vv = vb[(size_t)t * KM];
        const float bt = bb[t];
        const float dt = db[t];
        if (t + 1 < KS) {
            const float* qn = qb + (size_t)(t + 1) * KM;
            const float* kn = kb + (size_t)(t + 1) * KM;
            qa = *(const float4*)(qn);  qc = *(const float4*)(qn + 4);
            ka = *(const float4*)(kn);  kc = *(const float4*)(kn + 4);
        }
        float p = m[0]*cqa.x + m[1]*cqa.y + m[2]*cqa.z + m[3]*cqa.w
                + m[4]*cqc.x + m[5]*cqc.y + m[6]*cqc.z + m[7]*cqc.w;
        p = warp_sum(p);
        if (lane == 0) ro[(size_t)t * KM] = p;
        const float c = bt * vv;
        m[0] = dt*m[0] + c*cka.x;  m[1] = dt*m[1] + c*cka.y;
        m[2] = dt*m[2] + c*cka.z;  m[3] = dt*m[3] + c*cka.w;
        m[4] = dt*m[4] + c*ckc.x;  m[5] = dt*m[5] + c*ckc.y;
        m[6] = dt*m[6] + c*ckc.z;  m[7] = dt*m[7] + c*ckc.w;
    }
    *(float4*)(mem_out + mbase)     = make_float4(m[0], m[1], m[2], m[3]);
    *(float4*)(mem_out + mbase + 4) = make_float4(m[4], m[5], m[6], m[7]);
}

// ---------------- SGEMM: C[T,N] = A[T,K] @ W[N,K]^T (+bias, act, residual) -
// 128x128 tile, BK=8, 256 threads, 8x8 per-thread microtile.
#define BM 128
#define BN 128
#define BKK 8
#define TM 8
#define TN 8

template <int ACT, bool RES>   // ACT: 0 none, 1 gelu(exact), 2 tanh
__global__ void sgemm_kernel(const float* __restrict__ A, const float* __restrict__ W,
                             const float* __restrict__ bias, const float* __restrict__ res,
                             float* __restrict__ C, int T, int N, int K) {
    __shared__ float As[BKK][BM];
    __shared__ float Ws[BKK][BN + 4];

    const int tid = threadIdx.x;
    const int row0 = blockIdx.y * BM;
    const int col0 = blockIdx.x * BN;

    const int arow = tid >> 1;
    const int acol = (tid & 1) * 4;
    const int wrow = tid >> 1;
    const int wcol = (tid & 1) * 4;
    const float* Aptr = A + (size_t)(row0 + arow) * K + acol;
    const float* Wptr = W + (size_t)(col0 + wrow) * K + wcol;
    const bool wvalid = (col0 + wrow) < N;

    const int tx = tid & 15, ty = tid >> 4;

    float acc[TM][TN];
#pragma unroll
    for (int ii = 0; ii < TM; ii++)
#pragma unroll
        for (int jj = 0; jj < TN; jj++) acc[ii][jj] = 0.f;

    for (int k0 = 0; k0 < K; k0 += BKK) {
        const float4 av = *(const float4*)Aptr;
        const float4 wv = wvalid ? *(const float4*)Wptr : make_float4(0.f, 0.f, 0.f, 0.f);
        Aptr += BKK;
        Wptr += BKK;
        __syncthreads();
        As[acol + 0][arow] = av.x; As[acol + 1][arow] = av.y;
        As[acol + 2][arow] = av.z; As[acol + 3][arow] = av.w;
        Ws[wcol + 0][wrow] = wv.x; Ws[wcol + 1][wrow] = wv.y;
        Ws[wcol + 2][wrow] = wv.z; Ws[wcol + 3][wrow] = wv.w;
        __syncthreads();
#pragma unroll
        for (int kk = 0; kk < BKK; kk++) {
            float a[TM], w[TN];
            *(float4*)&a[0] = *(const float4*)&As[kk][ty * TM];
            *(float4*)&a[4] = *(const float4*)&As[kk][ty * TM + 4];
            *(float4*)&w[0] = *(const float4*)&Ws[kk][tx * TN];
            *(float4*)&w[4] = *(const float4*)&Ws[kk][tx * TN + 4];
#pragma unroll
            for (int ii = 0; ii < TM; ii++)
#pragma unroll
                for (int jj = 0; jj < TN; jj++) acc[ii][jj] += a[ii] * w[jj];
        }
    }

#pragma unroll
    for (int ii = 0; ii < TM; ii++) {
        const size_t r = (size_t)(row0 + ty * TM + ii);
#pragma unroll
        for (int jj = 0; jj < TN; jj += 4) {
            const int c = col0 + tx * TN + jj;
            if (c + 3 < N) {
                const float4 bv = *(const float4*)(bias + c);
                float4 o;
                o.x = acc[ii][jj + 0] + bv.x;
                o.y = acc[ii][jj + 1] + bv.y;
                o.z = acc[ii][jj + 2] + bv.z;
                o.w = acc[ii][jj + 3] + bv.w;
                if (ACT == 1) { o.x = gelu_exact(o.x); o.y = gelu_exact(o.y);
                                o.z = gelu_exact(o.z); o.w = gelu_exact(o.w); }
                else if (ACT == 2) { o.x = tanhf(o.x); o.y = tanhf(o.y);
                                     o.z = tanhf(o.z); o.w = tanhf(o.w); }
                if (RES) {
                    const float4 rv = *(const float4*)(res + r * N + c);
                    o.x += rv.x; o.y += rv.y; o.z += rv.z; o.w += rv.w;
                }
                *(float4*)(C + r * N + c) = o;
            } else {
#pragma unroll
                for (int e = 0; e < 4; e++) {
                    const int ce = c + e;
                    if (ce < N) {
                        float o = acc[ii][jj + e] + bias[ce];
                        if (ACT == 1) o = gelu_exact(o);
                        else if (ACT == 2) o = tanhf(o);
                        if (RES) o += res[r * N + ce];
                        C[r * N + ce] = o;
                    }
                }
            }
        }
    }
}

// ---------------- launch ----------------
extern "C" void kernel_launch(void* const* d_in, const int* in_sizes, int n_in,
                              void* d_out, int out_size) {
    (void)in_sizes; (void)n_in; (void)out_size;
    const float* x      = (const float*)d_in[0];
    const float* memory = (const float*)d_in[1];
    const float* w_k    = (const float*)d_in[2];
    const float* b_k    = (const float*)d_in[3];
    const float* w_q    = (const float*)d_in[4];
    const float* b_q    = (const float*)d_in[5];
    const float* w_v    = (const float*)d_in[6];
    const float* b_v    = (const float*)d_in[7];
    const float* w_out  = (const float*)d_in[8];
    const float* b_out  = (const float*)d_in[9];
    const float* w_gw   = (const float*)d_in[10];
    const float* b_gw   = (const float*)d_in[11];
    const float* w_gf   = (const float*)d_in[12];
    const float* b_gf   = (const float*)d_in[13];
    const float* ln1_g  = (const float*)d_in[14];
    const float* ln1_b  = (const float*)d_in[15];
    const float* ln2_g  = (const float*)d_in[16];
    const float* ln2_b  = (const float*)d_in[17];
    const float* w_f1   = (const float*)d_in[18];
    const float* b_f1   = (const float*)d_in[19];
    const float* w_f2   = (const float*)d_in[20];
    const float* b_f2   = (const float*)d_in[21];

    float* out_x   = (float*)d_out;
    float* out_mem = out_x + (size_t)KT * KE;

    float *p_xn, *p_k, *p_q, *p_v, *p_ro, *p_x2, *p_f1;
    cudaGetSymbolAddress((void**)&p_xn, g_xn);
    cudaGetSymbolAddress((void**)&p_k,  g_k);
    cudaGetSymbolAddress((void**)&p_q,  g_q);
    cudaGetSymbolAddress((void**)&p_v,  g_v);
    cudaGetSymbolAddress((void**)&p_ro, g_ro);
    cudaGetSymbolAddress((void**)&p_x2, g_x2);
    cudaGetSymbolAddress((void**)&p_f1, g_ffn1);

    const dim3 thr(256);

    // 1) LN1
    ln_kernel<<<KT, 256>>>(x, ln1_g, ln1_b, p_xn);
    // 2-4) k,q,v projections (+bias; v with tanh)
    sgemm_kernel<0, false><<<dim3(KM / BN, KT / BM), thr>>>(p_xn, w_k, b_k, nullptr, p_k, KT, KM, KE);
    sgemm_kernel<0, false><<<dim3(KM / BN, KT / BM), thr>>>(p_xn, w_q, b_q, nullptr, p_q, KT, KM, KE);
    sgemm_kernel<2, false><<<dim3(KM / BN, KT / BM), thr>>>(p_xn, w_v, b_v, nullptr, p_v, KT, KM, KE);
    // 5) normalize k,q; compute gates
    postproc_kernel<<<KT, 256>>>(w_gw, b_gw, w_gf, b_gf);
    // 6) sequential scan (row-parallel): readouts + final memory
    scan_kernel<<<KB * 32, 256>>>(memory, out_mem);
    // 7) out projection + residual -> x2
    sgemm_kernel<0, true><<<dim3(KE / BN, KT / BM), thr>>>(p_ro, w_out, b_out, x, p_x2, KT, KE, KM);
    // 8) LN2 (reuse g_xn)
    ln_kernel<<<KT, 256>>>(p_x2, ln2_g, ln2_b, p_xn);
    // 9) FFN1 + GELU
    sgemm_kernel<1, false><<<dim3(4 * KE / BN, KT / BM), thr>>>(p_xn, w_f1, b_f1, nullptr, p_f1, KT, 4 * KE, KE);
    // 10) FFN2 + residual -> out x
    sgemm_kernel<0, true><<<dim3(KE / BN, KT / BM), thr>>>(p_f1, w_f2, b_f2, p_x2, out_x, KT, KE, 4 * KE);
}

// round 3
// speedup vs baseline: 1.7786x; 1.7786x over previous
#include <cuda_runtime.h>
#include <cuda_bf16.h>
#include <math.h>
#include <stdint.h>

#define KB 4
#define KS 2048
#define KE 1024
#define KM 256
#define KF (4 * KE)
#define KT (KB * KS)   // 8192 tokens

// ---------------- scratch (device globals; no runtime allocation) ----------
__device__ __align__(16) float g_k [(size_t)KT * KM];
__device__ __align__(16) float g_q [(size_t)KT * KM];
__device__ __align__(16) float g_v [(size_t)KT * KM];
__device__ float g_beta [KT];
__device__ float g_decay[KT];
__device__ __align__(16) float g_x2[(size_t)KT * KE];

__device__ __align__(16) __nv_bfloat16 g_xn_hi[(size_t)KT * KE];
__device__ __align__(16) __nv_bfloat16 g_xn_lo[(size_t)KT * KE];
__device__ __align__(16) __nv_bfloat16 g_ro_hi[(size_t)KT * KM];
__device__ __align__(16) __nv_bfloat16 g_ro_lo[(size_t)KT * KM];
__device__ __align__(16) __nv_bfloat16 g_f1_hi[(size_t)KT * KF];
__device__ __align__(16) __nv_bfloat16 g_f1_lo[(size_t)KT * KF];

__device__ __align__(16) __nv_bfloat16 g_wk_hi[KM * KE],  g_wk_lo[KM * KE];
__device__ __align__(16) __nv_bfloat16 g_wq_hi[KM * KE],  g_wq_lo[KM * KE];
__device__ __align__(16) __nv_bfloat16 g_wv_hi[KM * KE],  g_wv_lo[KM * KE];
__device__ __align__(16) __nv_bfloat16 g_wo_hi[KE * KM],  g_wo_lo[KE * KM];
__device__ __align__(16) __nv_bfloat16 g_wf1_hi[(size_t)KF * KE], g_wf1_lo[(size_t)KF * KE];
__device__ __align__(16) __nv_bfloat16 g_wf2_hi[(size_t)KE * KF], g_wf2_lo[(size_t)KE * KF];

// ---------------- small helpers ----------------
__device__ __forceinline__ float warp_sum(float v) {
#pragma unroll
    for (int o = 16; o; o >>= 1) v += __shfl_xor_sync(0xffffffffu, v, o);
    return v;
}
__device__ __forceinline__ float gelu_exact(float v) {
    return 0.5f * v * (1.0f + erff(v * 0.70710678118654752f));
}
__device__ __forceinline__ uint16_t f2b(float x) {
    __nv_bfloat16 h = __float2bfloat16(x);
    return *reinterpret_cast<uint16_t*>(&h);
}
__device__ __forceinline__ float b2f(uint32_t u) {
    return __uint_as_float((u & 0xffffu) << 16);
}
__device__ __forceinline__ uint32_t s2u(const void* p) {
    uint32_t a;
    asm("{ .reg .u64 t; cvta.to.shared.u64 t, %1; cvt.u32.u64 %0, t; }" : "=r"(a) : "l"(p));
    return a;
}

// ---------------- PTX wrappers ----------------
__device__ __forceinline__ void cp16(uint32_t d, const void* g) {
    asm volatile("cp.async.cg.shared.global [%0], [%1], 16;\n" :: "r"(d), "l"(g));
}
__device__ __forceinline__ void cp_commit() { asm volatile("cp.async.commit_group;\n" ::: "memory"); }
template <int N> __device__ __forceinline__ void cp_wait() {
    asm volatile("cp.async.wait_group %0;\n" :: "n"(N) : "memory");
}
__device__ __forceinline__ void ldsm_x4(uint32_t& r0, uint32_t& r1, uint32_t& r2, uint32_t& r3,
                                        uint32_t addr) {
    asm volatile("ldmatrix.sync.aligned.m8n8.x4.shared.b16 {%0,%1,%2,%3}, [%4];"
                 : "=r"(r0), "=r"(r1), "=r"(r2), "=r"(r3) : "r"(addr));
}
__device__ __forceinline__ void mma_bf16(float& c0, float& c1, float& c2, float& c3,
                                         uint32_t a0, uint32_t a1, uint32_t a2, uint32_t a3,
                                         uint32_t b0, uint32_t b1) {
    asm volatile(
        "mma.sync.aligned.m16n8k16.row.col.f32.bf16.bf16.f32 "
        "{%0,%1,%2,%3}, {%4,%5,%6,%7}, {%8,%9}, {%0,%1,%2,%3};"
        : "+f"(c0), "+f"(c1), "+f"(c2), "+f"(c3)
        : "r"(a0), "r"(a1), "r"(a2), "r"(a3), "r"(b0), "r"(b1));
}

// ---------------- LayerNorm -> split bf16 hi/lo --------------------------
__global__ void ln_kernel(const float* __restrict__ x, const float* __restrict__ g,
                          const float* __restrict__ bvec,
                          __nv_bfloat16* __restrict__ yhi, __nv_bfloat16* __restrict__ ylo) {
    __shared__ float red[2][8];
    const int n = blockIdx.x;
    const int tid = threadIdx.x;
    const float4 xv = ((const float4*)(x + (size_t)n * KE))[tid];
    float s  = xv.x + xv.y + xv.z + xv.w;
    float ss = xv.x * xv.x + xv.y * xv.y + xv.z * xv.z + xv.w * xv.w;
    s = warp_sum(s); ss = warp_sum(ss);
    const int wid = tid >> 5, lane = tid & 31;
    if (lane == 0) { red[0][wid] = s; red[1][wid] = ss; }
    __syncthreads();
    float st = 0.f, sst = 0.f;
#pragma unroll
    for (int w = 0; w < 8; w++) { st += red[0][w]; sst += red[1][w]; }
    const float mu  = st * (1.0f / KE);
    const float var = sst * (1.0f / KE) - mu * mu;
    const float rs  = rsqrtf(var + 1e-5f);
    const float4 gg = ((const float4*)g)[tid];
    const float4 bb = ((const float4*)bvec)[tid];
    float o[4];
    o[0] = (xv.x - mu) * rs * gg.x + bb.x;
    o[1] = (xv.y - mu) * rs * gg.y + bb.y;
    o[2] = (xv.z - mu) * rs * gg.z + bb.z;
    o[3] = (xv.w - mu) * rs * gg.w + bb.w;
    uint16_t h[4], l[4];
#pragma unroll
    for (int e = 0; e < 4; e++) {
        h[e] = f2b(o[e]);
        l[e] = f2b(o[e] - b2f(h[e]));
    }
    const size_t vi = (size_t)n * 256 + tid;
    ((uint2*)yhi)[vi] = make_uint2((uint32_t)h[0] | ((uint32_t)h[1] << 16),
                                   (uint32_t)h[2] | ((uint32_t)h[3] << 16));
    ((uint2*)ylo)[vi] = make_uint2((uint32_t)l[0] | ((uint32_t)l[1] << 16),
                                   (uint32_t)l[2] | ((uint32_t)l[3] << 16));
}

// ---------------- generic fp32 -> bf16 hi/lo split ------------------------
__global__ void split_kernel(const float* __restrict__ src, __nv_bfloat16* __restrict__ hi,
                             __nv_bfloat16* __restrict__ lo, int n4) {
    const int i = blockIdx.x * 256 + threadIdx.x;
    if (i >= n4) return;
    const float4 v = ((const float4*)src)[i];
    float a[4] = {v.x, v.y, v.z, v.w};
    uint16_t h[4], l[4];
#pragma unroll
    for (int e = 0; e < 4; e++) {
        h[e] = f2b(a[e]);
        l[e] = f2b(a[e] - b2f(h[e]));
    }
    ((uint2*)hi)[i] = make_uint2((uint32_t)h[0] | ((uint32_t)h[1] << 16),
                                 (uint32_t)h[2] | ((uint32_t)h[3] << 16));
    ((uint2*)lo)[i] = make_uint2((uint32_t)l[0] | ((uint32_t)l[1] << 16),
                                 (uint32_t)l[2] | ((uint32_t)l[3] << 16));
}

// ---------------- postproc: l2norm k,q ; gates ----------------------------
__global__ void postproc_kernel(const float* __restrict__ wgw, const float* __restrict__ bgw,
                                const float* __restrict__ wgf, const float* __restrict__ bgf) {
    __shared__ float red[4][8];
    const int n = blockIdx.x;
    const int i = threadIdx.x;
    const size_t off = (size_t)n * KM + i;
    const float kv = g_k[off];
    const float qv = g_q[off];
    const size_t vi = (size_t)n * 256 + i;
    const uint2 hx = ((const uint2*)g_xn_hi)[vi];
    const uint2 lx = ((const uint2*)g_xn_lo)[vi];
    float xr[4];
    xr[0] = b2f(hx.x) + b2f(lx.x);
    xr[1] = b2f(hx.x >> 16) + b2f(lx.x >> 16);
    xr[2] = b2f(hx.y) + b2f(lx.y);
    xr[3] = b2f(hx.y >> 16) + b2f(lx.y >> 16);
    const float4 wg = ((const float4*)wgw)[i];
    const float4 wf = ((const float4*)wgf)[i];
    float dg = xr[0] * wg.x + xr[1] * wg.y + xr[2] * wg.z + xr[3] * wg.w;
    float df = xr[0] * wf.x + xr[1] * wf.y + xr[2] * wf.z + xr[3] * wf.w;
    float sk = warp_sum(kv * kv);
    float sq = warp_sum(qv * qv);
    dg = warp_sum(dg);
    df = warp_sum(df);
    const int wid = i >> 5, lane = i & 31;
    if (lane == 0) { red[0][wid] = sk; red[1][wid] = sq; red[2][wid] = dg; red[3][wid] = df; }
    __syncthreads();
    float tk = 0.f, tq = 0.f, tg = 0.f, tf = 0.f;
#pragma unroll
    for (int w = 0; w < 8; w++) { tk += red[0][w]; tq += red[1][w]; tg += red[2][w]; tf += red[3][w]; }
    const float kn = fmaxf(sqrtf(tk), 1e-12f);
    const float qn = fmaxf(sqrtf(tq), 1e-12f);
    g_k[off] = kv / kn;
    g_q[off] = qv / qn;
    if (i == 0) {
        g_beta[n]  = 1.0f / (1.0f + expf(-(tg + bgw[0])));
        g_decay[n] = 1.0f / (1.0f + expf(-(tf + bgf[0])));
    }
}

// ---------------- scan: one warp per (batch,row) ---------------------------
__global__ void scan_kernel(const float* __restrict__ mem0, float* __restrict__ mem_out) {
    const int blk = blockIdx.x;
    const int b = blk >> 5;
    const int i = ((blk & 31) << 3) + (threadIdx.x >> 5);
    const int lane = threadIdx.x & 31;
    const size_t mbase = (((size_t)b * KM + i) * KM) + lane * 8;

    float m[8];
    { float4 a = *(const float4*)(mem0 + mbase);
      float4 c = *(const float4*)(mem0 + mbase + 4);
      m[0]=a.x; m[1]=a.y; m[2]=a.z; m[3]=a.w; m[4]=c.x; m[5]=c.y; m[6]=c.z; m[7]=c.w; }

    const float* kb = g_k + ((size_t)b * KS) * KM + lane * 8;
    const float* qb = g_q + ((size_t)b * KS) * KM + lane * 8;
    const float* vb = g_v + ((size_t)b * KS) * KM + i;
    const float* bb = g_beta  + (size_t)b * KS;
    const float* db = g_decay + (size_t)b * KS;
    __nv_bfloat16* roh = g_ro_hi + ((size_t)b * KS) * KM + i;
    __nv_bfloat16* rol = g_ro_lo + ((size_t)b * KS) * KM + i;

    float4 qa = *(const float4*)(qb);
    float4 qc = *(const float4*)(qb + 4);
    float4 ka = *(const float4*)(kb);
    float4 kc = *(const float4*)(kb + 4);

    for (int t = 0; t < KS; t++) {
        const float4 cqa = qa, cqc = qc, cka = ka, ckc = kc;
        const float vv = vb[(size_t)t * KM];
        const float bt = bb[t];
        const float dt = db[t];
        if (t + 1 < KS) {
            const float* qn = qb + (size_t)(t + 1) * KM;
            const float* kn = kb + (size_t)(t + 1) * KM;
            qa = *(const float4*)(qn);  qc = *(const float4*)(qn + 4);
            ka = *(const float4*)(kn);  kc = *(const float4*)(kn + 4);
        }
        float p = m[0]*cqa.x + m[1]*cqa.y + m[2]*cqa.z + m[3]*cqa.w
                + m[4]*cqc.x + m[5]*cqc.y + m[6]*cqc.z + m[7]*cqc.w;
        p = warp_sum(p);
        if (lane == 0) {
            const uint16_t hh = f2b(p);
            roh[(size_t)t * KM] = *reinterpret_cast<const __nv_bfloat16*>(&hh);
            const uint16_t ll = f2b(p - b2f(hh));
            rol[(size_t)t * KM] = *reinterpret_cast<const __nv_bfloat16*>(&ll);
        }
        const float c = bt * vv;
        m[0] = dt*m[0] + c*cka.x;  m[1] = dt*m[1] + c*cka.y;
        m[2] = dt*m[2] + c*cka.z;  m[3] = dt*m[3] + c*cka.w;
        m[4] = dt*m[4] + c*ckc.x;  m[5] = dt*m[5] + c*ckc.y;
        m[6] = dt*m[6] + c*ckc.z;  m[7] = dt*m[7] + c*ckc.w;
    }
    *(float4*)(mem_out + mbase)     = make_float4(m[0], m[1], m[2], m[3]);
    *(float4*)(mem_out + mbase + 4) = make_float4(m[4], m[5], m[6], m[7]);
}

// ---------------- HMMA bf16x3 GEMM -----------------------------------------
// C[T,N] = A[T,K] @ W[N,K]^T via A_hi*B_hi + A_lo*B_hi + A_hi*B_lo
// 128x128 tile, BK=32, 256 threads (2x4 warps, 64x32 warp tiles),
// cp.async double buffer, mma.sync.m16n8k16 bf16, fp32 register accum.
// EPI: 0 = bias; 1 = bias+tanh; 2 = bias+residual; 3 = bias+gelu -> bf16 hi/lo
#define BKQ 32
#define LDS_PAD 8
#define ROWE (BKQ + LDS_PAD)   // 40 bf16 per row

template <int EPI>
__global__ void __launch_bounds__(256)
gemm_hmma(const __nv_bfloat16* __restrict__ Ahi, const __nv_bfloat16* __restrict__ Alo,
          const __nv_bfloat16* __restrict__ Bhi, const __nv_bfloat16* __restrict__ Blo,
          const float* __restrict__ bias, const float* __restrict__ res,
          float* __restrict__ Cf, __nv_bfloat16* __restrict__ Chi, __nv_bfloat16* __restrict__ Clo,
          int K, int N) {
    __shared__ __align__(16) __nv_bfloat16 As[2][128 * ROWE];
    __shared__ __align__(16) __nv_bfloat16 Bs[2][128 * ROWE];

    const int tid = threadIdx.x;
    const int wid = tid >> 5;
    const int lane = tid & 31;
    const int warp_m = wid >> 2;      // 0..1
    const int warp_n = wid & 3;       // 0..3

    const int row0 = blockIdx.y * 128;
    const int col0 = blockIdx.x * 128;
    const int kcs = K >> 5;           // BK=32 chunks per term
    const int nIters = 3 * kcs;

    const uint32_t sA0 = s2u(&As[0][0]);
    const uint32_t sB0 = s2u(&Bs[0][0]);
    const uint32_t bufStride = (uint32_t)(128 * ROWE * 2);

    // cp.async mapping: 512 chunks of 16B per tile; thread does 2 for A, 2 for B
    const int ld_row0 = tid >> 1;              // 0..127
    const int ld_c0   = (tid & 1) * 2;         // chunk 0/2  (each thread: c and c+1)

    auto load_stage = [&](int chunk, int buf) {
        const int t  = chunk / kcs;
        const int k0 = (chunk - t * kcs) << 5;
        const __nv_bfloat16* Asrc = (t == 1) ? Alo : Ahi;
        const __nv_bfloat16* Bsrc = (t == 2) ? Blo : Bhi;
        const uint32_t da = sA0 + buf * bufStride + (uint32_t)(ld_row0 * ROWE) * 2;
        const uint32_t db = sB0 + buf * bufStride + (uint32_t)(ld_row0 * ROWE) * 2;
        const __nv_bfloat16* ga = Asrc + (size_t)(row0 + ld_row0) * K + k0;
        const __nv_bfloat16* gb = Bsrc + (size_t)(col0 + ld_row0) * K + k0;
#pragma unroll
        for (int c = 0; c < 2; c++) {
            const int c16 = ld_c0 + c;
            cp16(da + c16 * 16, ga + c16 * 8);
            cp16(db + c16 * 16, gb + c16 * 8);
        }
    };

    float acc[4][4][4];
#pragma unroll
    for (int mt = 0; mt < 4; mt++)
#pragma unroll
        for (int nt = 0; nt < 4; nt++)
#pragma unroll
            for (int e = 0; e < 4; e++) acc[mt][nt][e] = 0.f;

    // ldmatrix per-lane offsets (element units within a tile)
    // A: row = warp_m*64 + mt*16 + lane%16 ; col = j*16 + (lane/16)*8
    const int a_row = warp_m * 64 + (lane & 15);
    const int a_col8 = (lane >> 4) * 8;
    // B: local = lane&7, sel = lane>>3:
    //    n = warp_n*32 + nt2*16 + ((sel>>1)&1)*8 + local ; k = j*16 + (sel&1)*8
    const int b_local = lane & 7;
    const int b_sel = lane >> 3;
    const int b_nrow = warp_n * 32 + ((b_sel >> 1) & 1) * 8 + b_local;
    const int b_k8 = (b_sel & 1) * 8;

    load_stage(0, 0);
    cp_commit();

    for (int it = 0; it < nIters; it++) {
        const int buf = it & 1;
        if (it + 1 < nIters) {
            load_stage(it + 1, 1 - buf);
            cp_commit();
            cp_wait<1>();
        } else {
            cp_wait<0>();
        }
        __syncthreads();

        const uint32_t sa = sA0 + buf * bufStride;
        const uint32_t sb = sB0 + buf * bufStride;
#pragma unroll
        for (int j = 0; j < 2; j++) {
            uint32_t a[4][4];
#pragma unroll
            for (int mt = 0; mt < 4; mt++) {
                const uint32_t addr = sa + (uint32_t)((a_row + mt * 16) * ROWE + j * 16 + a_col8) * 2;
                ldsm_x4(a[mt][0], a[mt][1], a[mt][2], a[mt][3], addr);
            }
            uint32_t b[4][2];
#pragma unroll
            for (int nt2 = 0; nt2 < 2; nt2++) {
                const uint32_t addr = sb + (uint32_t)((b_nrow + nt2 * 16) * ROWE + j * 16 + b_k8) * 2;
                uint32_t r0, r1, r2, r3;
                ldsm_x4(r0, r1, r2, r3, addr);
                b[nt2 * 2][0] = r0; b[nt2 * 2][1] = r1;
                b[nt2 * 2 + 1][0] = r2; b[nt2 * 2 + 1][1] = r3;
            }
#pragma unroll
            for (int mt = 0; mt < 4; mt++)
#pragma unroll
                for (int nt = 0; nt < 4; nt++)
                    mma_bf16(acc[mt][nt][0], acc[mt][nt][1], acc[mt][nt][2], acc[mt][nt][3],
                             a[mt][0], a[mt][1], a[mt][2], a[mt][3],
                             b[nt][0], b[nt][1]);
        }
        __syncthreads();
    }

    // ---- epilogue: registers -> global, fused bias/act/residual/split ----
    const int er = lane >> 2;          // row within 8
    const int ec = (lane & 3) * 2;     // col pair
#pragma unroll
    for (int nt = 0; nt < 4; nt++) {
        const int c = col0 + warp_n * 32 + nt * 8 + ec;
        const float b0 = __ldg(bias + c);
        const float b1 = __ldg(bias + c + 1);
#pragma unroll
        for (int mt = 0; mt < 4; mt++) {
            const int rl = row0 + warp_m * 64 + mt * 16 + er;
#pragma unroll
            for (int half = 0; half < 2; half++) {
                const size_t r = (size_t)(rl + half * 8);
                float v0 = acc[mt][nt][half * 2 + 0] + b0;
                float v1 = acc[mt][nt][half * 2 + 1] + b1;
                if (EPI == 1) { v0 = tanhf(v0); v1 = tanhf(v1); }
                if (EPI == 3) { v0 = gelu_exact(v0); v1 = gelu_exact(v1); }
                if (EPI <= 2) {
                    if (EPI == 2) {
                        const float2 rv = *(const float2*)(res + r * N + c);
                        v0 += rv.x; v1 += rv.y;
                    }
                    *(float2*)(Cf + r * N + c) = make_float2(v0, v1);
                } else {
                    const uint16_t h0 = f2b(v0), h1 = f2b(v1);
                    const uint16_t l0 = f2b(v0 - b2f(h0)), l1 = f2b(v1 - b2f(h1));
                    *(uint32_t*)(Chi + r * N + c) = (uint32_t)h0 | ((uint32_t)h1 << 16);
                    *(uint32_t*)(Clo + r * N + c) = (uint32_t)l0 | ((uint32_t)l1 << 16);
                }
            }
        }
    }
}

// ---------------- launch ----------------
extern "C" void kernel_launch(void* const* d_in, const int* in_sizes, int n_in,
                              void* d_out, int out_size) {
    (void)in_sizes; (void)n_in; (void)out_size;
    const float* x      = (const float*)d_in[0];
    const float* memory = (const float*)d_in[1];
    const float* w_k    = (const float*)d_in[2];
    const float* b_k    = (const float*)d_in[3];
    const float* w_q    = (const float*)d_in[4];
    const float* b_q    = (const float*)d_in[5];
    const float* w_v    = (const float*)d_in[6];
    const float* b_v    = (const float*)d_in[7];
    const float* w_out  = (const float*)d_in[8];
    const float* b_out  = (const float*)d_in[9];
    const float* w_gw   = (const float*)d_in[10];
    const float* b_gw   = (const float*)d_in[11];
    const float* w_gf   = (const float*)d_in[12];
    const float* b_gf   = (const float*)d_in[13];
    const float* ln1_g  = (const float*)d_in[14];
    const float* ln1_b  = (const float*)d_in[15];
    const float* ln2_g  = (const float*)d_in[16];
    const float* ln2_b  = (const float*)d_in[17];
    const float* w_f1   = (const float*)d_in[18];
    const float* b_f1   = (const float*)d_in[19];
    const float* w_f2   = (const float*)d_in[20];
    const float* b_f2   = (const float*)d_in[21];

    float* out_x   = (float*)d_out;
    float* out_mem = out_x + (size_t)KT * KE;

    float *p_k, *p_q, *p_v, *p_x2;
    __nv_bfloat16 *p_xnh, *p_xnl, *p_roh, *p_rol, *p_f1h, *p_f1l;
    __nv_bfloat16 *p_wkh, *p_wkl, *p_wqh, *p_wql, *p_wvh, *p_wvl;
    __nv_bfloat16 *p_woh, *p_wol, *p_wf1h, *p_wf1l, *p_wf2h, *p_wf2l;
    cudaGetSymbolAddress((void**)&p_k,    g_k);
    cudaGetSymbolAddress((void**)&p_q,    g_q);
    cudaGetSymbolAddress((void**)&p_v,    g_v);
    cudaGetSymbolAddress((void**)&p_x2,   g_x2);
    cudaGetSymbolAddress((void**)&p_xnh,  g_xn_hi);
    cudaGetSymbolAddress((void**)&p_xnl,  g_xn_lo);
    cudaGetSymbolAddress((void**)&p_roh,  g_ro_hi);
    cudaGetSymbolAddress((void**)&p_rol,  g_ro_lo);
    cudaGetSymbolAddress((void**)&p_f1h,  g_f1_hi);
    cudaGetSymbolAddress((void**)&p_f1l,  g_f1_lo);
    cudaGetSymbolAddress((void**)&p_wkh,  g_wk_hi);
    cudaGetSymbolAddress((void**)&p_wkl,  g_wk_lo);
    cudaGetSymbolAddress((void**)&p_wqh,  g_wq_hi);
    cudaGetSymbolAddress((void**)&p_wql,  g_wq_lo);
    cudaGetSymbolAddress((void**)&p_wvh,  g_wv_hi);
    cudaGetSymbolAddress((void**)&p_wvl,  g_wv_lo);
    cudaGetSymbolAddress((void**)&p_woh,  g_wo_hi);
    cudaGetSymbolAddress((void**)&p_wol,  g_wo_lo);
    cudaGetSymbolAddress((void**)&p_wf1h, g_wf1_hi);
    cudaGetSymbolAddress((void**)&p_wf1l, g_wf1_lo);
    cudaGetSymbolAddress((void**)&p_wf2h, g_wf2_hi);
    cudaGetSymbolAddress((void**)&p_wf2l, g_wf2_lo);

    // 1) LN1 -> xn hi/lo
    ln_kernel<<<KT, 256>>>(x, ln1_g, ln1_b, p_xnh, p_xnl);
    // 2) split weights
    split_kernel<<<(KM*KE/4 + 255)/256, 256>>>(w_k,   p_wkh,  p_wkl,  KM*KE/4);
    split_kernel<<<(KM*KE/4 + 255)/256, 256>>>(w_q,   p_wqh,  p_wql,  KM*KE/4);
    split_kernel<<<(KM*KE/4 + 255)/256, 256>>>(w_v,   p_wvh,  p_wvl,  KM*KE/4);
    split_kernel<<<(KE*KM/4 + 255)/256, 256>>>(w_out, p_woh,  p_wol,  KE*KM/4);
    split_kernel<<<(KF*KE/4 + 255)/256, 256>>>(w_f1,  p_wf1h, p_wf1l, KF*KE/4);
    split_kernel<<<(KE*KF/4 + 255)/256, 256>>>(w_f2,  p_wf2h, p_wf2l, KE*KF/4);
    // 3) k,q,v projections
    gemm_hmma<0><<<dim3(KM/128, KT/128), 256>>>(
        p_xnh, p_xnl, p_wkh, p_wkl, b_k, nullptr, p_k, nullptr, nullptr, KE, KM);
    gemm_hmma<0><<<dim3(KM/128, KT/128), 256>>>(
        p_xnh, p_xnl, p_wqh, p_wql, b_q, nullptr, p_q, nullptr, nullptr, KE, KM);
    gemm_hmma<1><<<dim3(KM/128, KT/128), 256>>>(
        p_xnh, p_xnl, p_wvh, p_wvl, b_v, nullptr, p_v, nullptr, nullptr, KE, KM);
    // 4) l2norm + gates
    postproc_kernel<<<KT, 256>>>(w_gw, b_gw, w_gf, b_gf);
    // 5) scan -> readouts (bf16 hi/lo) + final memory
    scan_kernel<<<KB * 32, 256>>>(memory, out_mem);
    // 6) out projection + residual(x) -> x2 (fp32)
    gemm_hmma<2><<<dim3(KE/128, KT/128), 256>>>(
        p_roh, p_rol, p_woh, p_wol, b_out, x, p_x2, nullptr, nullptr, KM, KE);
    // 7) LN2 -> xn hi/lo (reuse)
    ln_kernel<<<KT, 256>>>(p_x2, ln2_g, ln2_b, p_xnh, p_xnl);
    // 8) FFN1 + GELU -> f1 hi/lo
    gemm_hmma<3><<<dim3(KF/128, KT/128), 256>>>(
        p_xnh, p_xnl, p_wf1h, p_wf1l, b_f1, nullptr, nullptr, p_f1h, p_f1l, KE, KF);
    // 9) FFN2 + residual(x2) -> out
    gemm_hmma<2><<<dim3(KE/128, KT/128), 256>>>(
        p_f1h, p_f1l, p_wf2h, p_wf2l, b_f2, p_x2, out_x, nullptr, nullptr, KF, KE);
}